// round 12
// baseline (speedup 1.0000x reference)
#include <cuda_runtime.h>
#include <cstdint>
#include <cstddef>

#define HD 1024
#define BA 64
#define TS 256
#define NL 4
#define MR (BA*TS)
#define NCTA 128
#define GP 24        // gemm smem pitch (bf16 units)
#define RP 1032      // recur smem pitch (bf16 units) -> conflict-free

// ---------------- device scratch ----------------
__device__ float    g_A[(size_t)MR * HD];
__device__ float2   g_st2[32 * BA];               // [ng][abs row 0..63]
__device__ unsigned g_bar4[4][4][32];             // [bg][event SA,SB,HA,HB][pad]
__device__ uint16_t g_Xh[(size_t)MR * HD];        // x hi plane
__device__ uint16_t g_Xl[(size_t)MR * HD];        // x lo plane
__device__ uint16_t g_Wph[(size_t)5 * HD * HD];   // 5 weight hi planes
__device__ uint16_t g_Wpl[(size_t)5 * HD * HD];   // 5 weight lo planes
__device__ uint16_t g_hbH[8 * 8 * HD];            // h hi plane: [group 0..7][8 rows][1024 f]
__device__ uint16_t g_hbL[8 * 8 * HD];            // h lo plane

typedef unsigned long long ull;

__device__ __forceinline__ unsigned ldacq(const unsigned* p) {
    unsigned v; asm volatile("ld.acquire.gpu.u32 %0, [%1];" : "=r"(v) : "l"(p)); return v;
}
__device__ __forceinline__ void redrel(unsigned* p) {
    asm volatile("red.release.gpu.global.add.u32 [%0], 1;" :: "l"(p));
}
__device__ __forceinline__ void cpa16(void* dst, const void* src) {
    uint32_t d = (uint32_t)__cvta_generic_to_shared(dst);
    asm volatile("cp.async.cg.shared.global [%0], [%1], 16;" :: "r"(d), "l"(src));
}
__device__ __forceinline__ uint16_t bf16_bits(float x) {
    uint32_t u = __float_as_uint(x);
    return (uint16_t)((u + 0x7fffu + ((u >> 16) & 1u)) >> 16);
}
__device__ __forceinline__ float bf16f(uint16_t b) {
    return __uint_as_float(((uint32_t)b) << 16);
}
__device__ __forceinline__ void mma_bf16(float c[4], const uint32_t a[4], const uint32_t b[2]) {
    asm volatile(
        "mma.sync.aligned.m16n8k16.row.col.f32.bf16.bf16.f32 "
        "{%0,%1,%2,%3}, {%4,%5,%6,%7}, {%8,%9}, {%0,%1,%2,%3};"
        : "+f"(c[0]), "+f"(c[1]), "+f"(c[2]), "+f"(c[3])
        : "r"(a[0]), "r"(a[1]), "r"(a[2]), "r"(a[3]), "r"(b[0]), "r"(b[1]));
}

// =====================================================================
// fp32 -> (hi, lo) bf16 planes
// =====================================================================
__global__ void conv_split(const float* __restrict__ src,
                           uint16_t* __restrict__ hi, uint16_t* __restrict__ lo, int n4)
{
    for (int i = blockIdx.x * blockDim.x + threadIdx.x; i < n4; i += gridDim.x * blockDim.x) {
        float4 v = __ldcg((const float4*)src + i);
        uint16_t h0 = bf16_bits(v.x), h1 = bf16_bits(v.y);
        uint16_t h2 = bf16_bits(v.z), h3 = bf16_bits(v.w);
        uint16_t l0 = bf16_bits(v.x - bf16f(h0)), l1 = bf16_bits(v.y - bf16f(h1));
        uint16_t l2 = bf16_bits(v.z - bf16f(h2)), l3 = bf16_bits(v.w - bf16f(h3));
        ull hp = (ull)h0 | ((ull)h1 << 16) | ((ull)h2 << 32) | ((ull)h3 << 48);
        ull lp = (ull)l0 | ((ull)l1 << 16) | ((ull)l2 << 32) | ((ull)l3 << 48);
        ((ull*)hi)[i] = hp;
        ((ull*)lo)[i] = lp;
    }
}

// =====================================================================
// Tensor-core split-bf16 GEMM (validated): out = X @ W^T + bias
// =====================================================================
__global__ __launch_bounds__(256, 2) void gemm_tc(
    const uint16_t* __restrict__ Xh, const uint16_t* __restrict__ Xl,
    const uint16_t* __restrict__ Wh, const uint16_t* __restrict__ Wl,
    const float* __restrict__ bias, float* __restrict__ out)
{
    __shared__ uint16_t sm[2][4][128 * GP];

    const int tid = threadIdx.x;
    const int bn = blockIdx.x, bm = blockIdx.y;
    const int warp = tid >> 5, lane = tid & 31;
    const int g = lane >> 2, tq = lane & 3;
    const int wm = warp >> 1, wn = warp & 1;

    const uint16_t* gsrc[4];
    int pl[4], dof[4];
    #pragma unroll
    for (int j = 0; j < 4; j++) {
        int lin = j * 256 + tid;
        int plane = lin >> 8, rem = lin & 255;
        int row = rem >> 1, half = rem & 1;
        pl[j] = plane; dof[j] = row * GP + half * 8;
        const uint16_t* base;
        if      (plane == 0) base = Xh + (size_t)(bm * 128 + row) * HD;
        else if (plane == 1) base = Xl + (size_t)(bm * 128 + row) * HD;
        else if (plane == 2) base = Wh + (size_t)(bn * 128 + row) * HD;
        else                 base = Wl + (size_t)(bn * 128 + row) * HD;
        gsrc[j] = base + half * 8;
    }
    auto issue = [&](int buf, int c) {
        int k0 = c * 16;
        #pragma unroll
        for (int j = 0; j < 4; j++) cpa16(&sm[buf][pl[j]][dof[j]], gsrc[j] + k0);
        asm volatile("cp.async.commit_group;");
    };

    float acc[2][8][4];
    #pragma unroll
    for (int mt = 0; mt < 2; mt++)
        #pragma unroll
        for (int nt = 0; nt < 8; nt++)
            #pragma unroll
            for (int j = 0; j < 4; j++) acc[mt][nt][j] = 0.f;

    issue(0, 0);
    const int NCH = HD / 16;
    for (int c = 0; c < NCH; c++) {
        const int cur = c & 1;
        if (c + 1 < NCH) {
            issue(cur ^ 1, c + 1);
            asm volatile("cp.async.wait_group 1;");
        } else {
            asm volatile("cp.async.wait_group 0;");
        }
        __syncthreads();

        uint32_t aH[2][4], aL[2][4];
        #pragma unroll
        for (int mt = 0; mt < 2; mt++) {
            int row = wm * 32 + mt * 16 + g;
            aH[mt][0] = *(const uint32_t*)&sm[cur][0][row * GP + 2 * tq];
            aH[mt][1] = *(const uint32_t*)&sm[cur][0][(row + 8) * GP + 2 * tq];
            aH[mt][2] = *(const uint32_t*)&sm[cur][0][row * GP + 8 + 2 * tq];
            aH[mt][3] = *(const uint32_t*)&sm[cur][0][(row + 8) * GP + 8 + 2 * tq];
            aL[mt][0] = *(const uint32_t*)&sm[cur][1][row * GP + 2 * tq];
            aL[mt][1] = *(const uint32_t*)&sm[cur][1][(row + 8) * GP + 2 * tq];
            aL[mt][2] = *(const uint32_t*)&sm[cur][1][row * GP + 8 + 2 * tq];
            aL[mt][3] = *(const uint32_t*)&sm[cur][1][(row + 8) * GP + 8 + 2 * tq];
        }
        #pragma unroll
        for (int nt = 0; nt < 8; nt++) {
            int n = wn * 64 + nt * 8 + g;
            uint32_t bH[2], bL[2];
            bH[0] = *(const uint32_t*)&sm[cur][2][n * GP + 2 * tq];
            bH[1] = *(const uint32_t*)&sm[cur][2][n * GP + 8 + 2 * tq];
            bL[0] = *(const uint32_t*)&sm[cur][3][n * GP + 2 * tq];
            bL[1] = *(const uint32_t*)&sm[cur][3][n * GP + 8 + 2 * tq];
            #pragma unroll
            for (int mt = 0; mt < 2; mt++) {
                mma_bf16(acc[mt][nt], aH[mt], bH);
                mma_bf16(acc[mt][nt], aH[mt], bL);
                mma_bf16(acc[mt][nt], aL[mt], bH);
            }
        }
        __syncthreads();
    }

    #pragma unroll
    for (int mt = 0; mt < 2; mt++) {
        int row = bm * 128 + wm * 32 + mt * 16 + g;
        #pragma unroll
        for (int nt = 0; nt < 8; nt++) {
            int col = bn * 128 + wn * 64 + nt * 8 + 2 * tq;
            float b0 = __ldg(bias + col), b1 = __ldg(bias + col + 1);
            *(float2*)&out[(size_t)row * HD + col] =
                make_float2(acc[mt][nt][0] + b0, acc[mt][nt][1] + b1);
            *(float2*)&out[(size_t)(row + 8) * HD + col] =
                make_float2(acc[mt][nt][2] + b0, acc[mt][nt][3] + b1);
        }
    }
}

// =====================================================================
// Recurrence v3: two phase-shifted 8-row groups per CTA, transposed mma.
// 128 CTAs = 4 domains x 32 feature-groups; domain bg serves row-groups
// bg (rows 8bg..) and bg+4 (rows 32+8bg..). z^T = Wslice @ h^T:
// M=32 features (2 x m16, warp ft), N=8 rows, K=1024 (4 warp-quarters kq).
// =====================================================================
__global__ void rst_bar() {
    int i = threadIdx.x;
    if (i < 16) g_bar4[i >> 2][i & 3][0] = 0u;
}

#define RSMEM (96 * RP * 2)   // WsH/WsL 32 rows + 4 x 8-row Hs planes = 198144 B

__global__ __launch_bounds__(256, 1) void recur(
    const float* __restrict__ A, const float* __restrict__ Wh,
    const float* __restrict__ lng, const float* __restrict__ lnb,
    uint16_t* __restrict__ xh, uint16_t* __restrict__ xl,
    float* __restrict__ xout)
{
    extern __shared__ char dsm[];
    uint16_t* WsH  = (uint16_t*)dsm;          // [32][RP]
    uint16_t* WsL  = WsH + 32 * RP;
    uint16_t* HsAH = WsL + 32 * RP;           // [8][RP]
    uint16_t* HsAL = HsAH + 8 * RP;
    uint16_t* HsBH = HsAL + 8 * RP;
    uint16_t* HsBL = HsBH + 8 * RP;
    __shared__ float4 red[3][2][32];
    __shared__ float2 sst[2][8];
    __shared__ float s_mu[8], s_rs[8], s_g[32], s_b[32];

    const int tid = threadIdx.x, cta = blockIdx.x;
    const int bg = cta >> 5, ng = cta & 31;
    const int n0 = ng * 32;
    const int warp = tid >> 5, lane = tid & 31;
    const int ft = warp & 1, kq = warp >> 1;
    const int g = lane >> 2, tq = lane & 3;
    const int grpA = bg, grpB = bg + 4;
    const int R0A = grpA * 8, R0B = grpB * 8;   // absolute batch-row bases

    // ---- prologue ----
    for (int idx = tid; idx < 32 * 512; idx += 256) {
        int f = idx >> 9, k = (idx & 511) * 2;
        float2 v = *(const float2*)&Wh[(size_t)(n0 + f) * HD + k];
        uint16_t h0 = bf16_bits(v.x), h1 = bf16_bits(v.y);
        uint16_t l0 = bf16_bits(v.x - bf16f(h0)), l1 = bf16_bits(v.y - bf16f(h1));
        *(uint32_t*)&WsH[f * RP + k] = (uint32_t)h0 | ((uint32_t)h1 << 16);
        *(uint32_t*)&WsL[f * RP + k] = (uint32_t)l0 | ((uint32_t)l1 << 16);
    }
    if (tid < 32) { s_g[tid] = lng[n0 + tid]; s_b[tid] = lnb[n0 + tid]; }
    {   // zero our feature slice of both groups' h planes
        int r = tid >> 5, f = tid & 31;
        int oA = (grpA * 8 + r) * HD + n0 + f;
        int oB = (grpB * 8 + r) * HD + n0 + f;
        g_hbH[oA] = 0; g_hbL[oA] = 0;
        g_hbH[oB] = 0; g_hbL[oB] = 0;
    }
    __syncthreads();
    unsigned* bSA = &g_bar4[bg][0][0];
    unsigned* bSB = &g_bar4[bg][1][0];
    unsigned* bHA = &g_bar4[bg][2][0];
    unsigned* bHB = &g_bar4[bg][3][0];
    if (tid == 0) { __threadfence(); redrel(bHA); redrel(bHB); }

    auto wbar = [&](unsigned* p, unsigned tg) {
        __syncthreads();
        if (tid == 0) { while (ldacq(p) < tg) { } }
        __syncthreads();
    };
    auto fill = [&](int grp, uint16_t* dH, uint16_t* dL) {
        #pragma unroll
        for (int j = 0; j < 8; j++) {
            int lin = j * 256 + tid;
            int pl = lin >> 10, rem = lin & 1023;
            int row = rem >> 7, c = rem & 127;
            const uint16_t* src = (pl ? g_hbL : g_hbH) + ((size_t)(grp * 8 + row) * HD + c * 8);
            uint16_t* dst = (pl ? dL : dH) + row * RP + c * 8;
            cpa16(dst, src);
        }
        asm volatile("cp.async.commit_group;");
    };
    auto domma = [&](const uint16_t* HH, const uint16_t* HL, float acc[4]) {
        acc[0] = acc[1] = acc[2] = acc[3] = 0.f;
        const int r0 = (ft * 16 + g) * RP, r1 = (ft * 16 + g + 8) * RP;
        const int hr = g * RP;
        #pragma unroll 4
        for (int ks = 0; ks < 16; ks++) {
            int kk = kq * 256 + ks * 16 + 2 * tq;
            uint32_t aH[4], aL[4], bH[2], bL[2];
            aH[0] = *(const uint32_t*)&WsH[r0 + kk];
            aH[1] = *(const uint32_t*)&WsH[r1 + kk];
            aH[2] = *(const uint32_t*)&WsH[r0 + kk + 8];
            aH[3] = *(const uint32_t*)&WsH[r1 + kk + 8];
            aL[0] = *(const uint32_t*)&WsL[r0 + kk];
            aL[1] = *(const uint32_t*)&WsL[r1 + kk];
            aL[2] = *(const uint32_t*)&WsL[r0 + kk + 8];
            aL[3] = *(const uint32_t*)&WsL[r1 + kk + 8];
            bH[0] = *(const uint32_t*)&HH[hr + kk];
            bH[1] = *(const uint32_t*)&HH[hr + kk + 8];
            bL[0] = *(const uint32_t*)&HL[hr + kk];
            bL[1] = *(const uint32_t*)&HL[hr + kk + 8];
            mma_bf16(acc, aH, bH);
            mma_bf16(acc, aH, bL);
            mma_bf16(acc, aL, bH);
        }
    };
    // K-reduce + stats publish.  acc lane map: c0=(f0,r0) c1=(f0,r1) c2=(f1,r0) c3=(f1,r1)
    auto redpub = [&](float acc[4], const float at[4], int R0, unsigned* bS) {
        if (kq > 0) red[kq - 1][ft][lane] = make_float4(acc[0], acc[1], acc[2], acc[3]);
        __syncthreads();
        if (kq == 0) {
            #pragma unroll
            for (int j = 0; j < 3; j++) {
                float4 v = red[j][ft][lane];
                acc[0] += v.x; acc[1] += v.y; acc[2] += v.z; acc[3] += v.w;
            }
            acc[0] += at[0]; acc[1] += at[1]; acc[2] += at[2]; acc[3] += at[3];
            float s0 = acc[0] + acc[2], q0 = acc[0]*acc[0] + acc[2]*acc[2];
            float s1 = acc[1] + acc[3], q1 = acc[1]*acc[1] + acc[3]*acc[3];
            #pragma unroll
            for (int m = 4; m <= 16; m <<= 1) {
                s0 += __shfl_xor_sync(0xffffffffu, s0, m);
                q0 += __shfl_xor_sync(0xffffffffu, q0, m);
                s1 += __shfl_xor_sync(0xffffffffu, s1, m);
                q1 += __shfl_xor_sync(0xffffffffu, q1, m);
            }
            if (g == 0) {
                sst[ft][2 * tq]     = make_float2(s0, q0);
                sst[ft][2 * tq + 1] = make_float2(s1, q1);
            }
        }
        __syncthreads();
        if (tid < 8) {
            float2 a = sst[0][tid], b = sst[1][tid];
            *(float2*)&g_st2[ng * BA + R0 + tid] = make_float2(a.x + b.x, a.y + b.y);
        }
        __syncthreads();
        if (tid == 0) { __threadfence(); redrel(bS); }
    };
    auto epi = [&](float acc[4], int R0, int grp, unsigned* bS, unsigned* bH_, unsigned t) {
        wbar(bS, 32u * (t + 1));
        if (tid < 64) {
            int row = tid >> 3, oct = tid & 7;
            float ss = 0.f, qq = 0.f;
            #pragma unroll
            for (int m = 0; m < 4; m++) {
                float2 v = __ldcg((const float2*)&g_st2[(oct * 4 + m) * BA + R0 + row]);
                ss += v.x; qq += v.y;
            }
            #pragma unroll
            for (int m = 1; m <= 4; m <<= 1) {
                ss += __shfl_xor_sync(0xffffffffu, ss, m);
                qq += __shfl_xor_sync(0xffffffffu, qq, m);
            }
            if (oct == 0) {
                float mu = ss * (1.f / HD);
                float var = qq * (1.f / HD) - mu * mu;
                s_mu[row] = mu;
                s_rs[row] = rsqrtf(var + 1e-5f);
            }
        }
        __syncthreads();
        if (kq == 0) {
            int r0 = 2 * tq, r1 = r0 + 1;
            int f0 = ft * 16 + g, f1 = f0 + 8;
            float mu0 = s_mu[r0], rs0 = s_rs[r0], mu1 = s_mu[r1], rs1 = s_rs[r1];
            float ga0 = s_g[f0], be0 = s_b[f0], ga1 = s_g[f1], be1 = s_b[f1];
            float h00 = tanhf((acc[0] - mu0) * rs0 * ga0 + be0);   // (f0, r0)
            float h01 = tanhf((acc[1] - mu1) * rs1 * ga0 + be0);   // (f0, r1)
            float h10 = tanhf((acc[2] - mu0) * rs0 * ga1 + be1);   // (f1, r0)
            float h11 = tanhf((acc[3] - mu1) * rs1 * ga1 + be1);   // (f1, r1)
            int fa0 = n0 + f0, fa1 = n0 + f1;
            size_t x00 = ((size_t)(R0 + r0) * TS + t) * HD + fa0;
            size_t x01 = ((size_t)(R0 + r1) * TS + t) * HD + fa0;
            size_t x10 = x00 + 8, x11 = x01 + 8;
            uint16_t i00 = bf16_bits(h00), i01 = bf16_bits(h01);
            uint16_t i10 = bf16_bits(h10), i11 = bf16_bits(h11);
            uint16_t l00 = bf16_bits(h00 - bf16f(i00)), l01 = bf16_bits(h01 - bf16f(i01));
            uint16_t l10 = bf16_bits(h10 - bf16f(i10)), l11 = bf16_bits(h11 - bf16f(i11));
            xh[x00] = i00; xh[x01] = i01; xh[x10] = i10; xh[x11] = i11;
            xl[x00] = l00; xl[x01] = l01; xl[x10] = l10; xl[x11] = l11;
            int o00 = (grp * 8 + r0) * HD + fa0, o01 = (grp * 8 + r1) * HD + fa0;
            int o10 = o00 + 8, o11 = o01 + 8;
            g_hbH[o00] = i00; g_hbH[o01] = i01; g_hbH[o10] = i10; g_hbH[o11] = i11;
            g_hbL[o00] = l00; g_hbL[o01] = l01; g_hbL[o10] = l10; g_hbL[o11] = l11;
            if (xout) {
                xout[x00] = h00; xout[x01] = h01; xout[x10] = h10; xout[x11] = h11;
            }
        }
        __syncthreads();
        if (tid == 0) { __threadfence(); redrel(bH_); }
    };

    for (unsigned t = 0; t < TS; t++) {
        float atA[4], atB[4];
        // (a) group A: wait h, prefetch A-term, issue fill
        wbar(bHA, 32u * (t + 1));
        if (kq == 0) {
            size_t b0 = ((size_t)(R0A + 2 * tq) * TS + t) * HD + n0 + ft * 16 + g;
            size_t b1 = b0 + (size_t)TS * HD;
            atA[0] = __ldcg(&A[b0]); atA[2] = __ldcg(&A[b0 + 8]);
            atA[1] = __ldcg(&A[b1]); atA[3] = __ldcg(&A[b1 + 8]);
        }
        fill(grpA, HsAH, HsAL);
        // (a') group B: wait h, prefetch, issue fill
        wbar(bHB, 32u * (t + 1));
        if (kq == 0) {
            size_t b0 = ((size_t)(R0B + 2 * tq) * TS + t) * HD + n0 + ft * 16 + g;
            size_t b1 = b0 + (size_t)TS * HD;
            atB[0] = __ldcg(&A[b0]); atB[2] = __ldcg(&A[b0 + 8]);
            atB[1] = __ldcg(&A[b1]); atB[3] = __ldcg(&A[b1 + 8]);
        }
        fill(grpB, HsBH, HsBL);

        // (b) mma A   (B's fill still in flight)
        asm volatile("cp.async.wait_group 1;");
        __syncthreads();
        float accA[4];
        domma(HsAH, HsAL, accA);
        // (c) reduce + publish stats A
        redpub(accA, atA, R0A, bSA);

        // (e) mma B
        asm volatile("cp.async.wait_group 0;");
        __syncthreads();
        float accB[4];
        domma(HsBH, HsBL, accB);
        // (f) reduce + publish stats B
        redpub(accB, atB, R0B, bSB);

        // (g)(h) epilogues: consume stats, publish h(t+1)
        epi(accA, R0A, grpA, bSA, bHA, t);
        epi(accB, R0B, grpB, bSB, bHB, t);
    }
}

// =====================================================================
extern "C" void kernel_launch(void* const* d_in, const int* in_sizes, int n_in,
                              void* d_out, int out_size)
{
    const float* inputs = (const float*)d_in[0];
    const float* Wx     = (const float*)d_in[1];
    const float* bx     = (const float*)d_in[2];
    const float* Wh     = (const float*)d_in[3];
    const float* lng    = (const float*)d_in[4];
    const float* lnb    = (const float*)d_in[5];
    const float* Wy     = (const float*)d_in[6];
    const float* by     = (const float*)d_in[7];

    float* out_x = (float*)d_out;
    float* out_y = out_x + (size_t)MR * HD;

    float* pA = nullptr;
    uint16_t *pXh, *pXl, *pWh, *pWl;
    cudaGetSymbolAddress((void**)&pA, g_A);
    cudaGetSymbolAddress((void**)&pXh, g_Xh);
    cudaGetSymbolAddress((void**)&pXl, g_Xl);
    cudaGetSymbolAddress((void**)&pWh, g_Wph);
    cudaGetSymbolAddress((void**)&pWl, g_Wpl);

    cudaFuncSetAttribute(recur, cudaFuncAttributeMaxDynamicSharedMemorySize, RSMEM);

    dim3 ggrid(8, 128);
    const int NX4 = MR * HD / 4, NW4 = HD * HD / 4;
    const size_t WOF = (size_t)HD * HD;

    conv_split<<<1024, 256>>>(inputs, pXh, pXl, NX4);
    for (int l = 0; l < NL; l++)
        conv_split<<<512, 256>>>(Wx + l * WOF, pWh + l * WOF, pWl + l * WOF, NW4);
    conv_split<<<512, 256>>>(Wy, pWh + 4 * WOF, pWl + 4 * WOF, NW4);

    for (int l = 0; l < NL; l++) {
        gemm_tc<<<ggrid, 256>>>(pXh, pXl, pWh + l * WOF, pWl + l * WOF,
                                bx + (size_t)l * HD, pA);
        rst_bar<<<1, 32>>>();
        float* xo = (l == NL - 1) ? out_x : nullptr;
        recur<<<NCTA, 256, RSMEM>>>(pA, Wh + l * WOF,
                                    lng + (size_t)l * HD, lnb + (size_t)l * HD,
                                    pXh, pXl, xo);
    }
    gemm_tc<<<ggrid, 256>>>(pXh, pXl, pWh + 4 * WOF, pWl + 4 * WOF, by, out_y);
}